// round 10
// baseline (speedup 1.0000x reference)
#include <cuda_runtime.h>
#include <cuda_bf16.h>

// ---------------------------------------------------------------------------
// EMD loss (multiplicative Sinkhorn, 2*eps == 1), full tensor-core core.
//   C = row-minmax-norm(1 - cos(x1[i],x2[i]))   [tf32 mma.m16n8k8]
//   E = exp(-2C);  eu0 = q1/rowsum(E);
//   {ev = q2/(eu@E) ; eu = q1/(ev@E^T)} x4 ; ev = q2/(eu@E)   [bf16 HMMA]
//   loss += eu^T (E.*C) ev                                     [bf16 HMMA]
// 256 blocks x 256 threads: each block owns 32 of the 64 a-rows of one
// (pair,i) problem (C/E build duplicated across the 2 sibling blocks).
// ~70KB smem -> 2 blocks/SM co-resident: independent streams overlap the
// latency-bound phases. Sinkhorn syncs via 2 row-group named barriers.
// ---------------------------------------------------------------------------

#define SMEM_BYTES 71680

#define OB_X1    0        // f32(tf32) x1 [j][h] stride 68 (17408); later E/ET
#define OB_X2    17408    // f32(tf32) x2 [k][h] stride 68 (17408); later ET/G
#define OB_C     34816    // f32 C [j][k] stride 68        (17408)
#define OB_EB    0        // bf16 E  [j][k] stride 72      (9216)   aliases X1
#define OB_ETB   9216     // bf16 E^T [k][j] stride 74     (9472)   aliases X1/X2
#define OB_GB    18688    // bf16 E.*C [j][k] stride 72    (9216)   aliases X2
#define OB_Q1B   52224    // bf16 q1 [32][j] stride 72     (4608)
#define OB_Q2B   56832    // bf16 q2 [32][k]               (4608)
#define OB_EUB   61440    // bf16 eu [32][j]               (4608)
#define OB_EVB   66048    // bf16 ev [32][k]               (4608)
#define OB_I1    70656
#define OB_I2    70912
#define OB_RS    71168
#define OB_RED   71424
#define OB_FLAG  71460

#define STF 68            // fp32 row stride (words)
#define STW 36            // bf16 row stride in 32-bit words
#define STTW 37           // ET row stride in words

__device__ float g_partials[256];
__device__ unsigned int g_count = 0;

__device__ __forceinline__ float tf32r(float x) {
    float r; asm("cvt.rna.tf32.f32 %0, %1;" : "=f"(r) : "f"(x)); return r;
}

__device__ __forceinline__ void mma_bf16(float c[4], unsigned a0, unsigned a1,
                                         unsigned a2, unsigned a3,
                                         unsigned b0, unsigned b1)
{
    asm volatile(
        "mma.sync.aligned.m16n8k16.row.col.f32.bf16.bf16.f32 "
        "{%0,%1,%2,%3}, {%4,%5,%6,%7}, {%8,%9}, {%0,%1,%2,%3};"
        : "+f"(c[0]), "+f"(c[1]), "+f"(c[2]), "+f"(c[3])
        : "r"(a0), "r"(a1), "r"(a2), "r"(a3), "r"(b0), "r"(b1));
}

__device__ __forceinline__ void mma_tf32(float c[4], float a0, float a1,
                                         float a2, float a3, float b0, float b1)
{
    asm volatile(
        "mma.sync.aligned.m16n8k8.row.col.f32.tf32.tf32.f32 "
        "{%0,%1,%2,%3}, {%4,%5,%6,%7}, {%8,%9}, {%0,%1,%2,%3};"
        : "+f"(c[0]), "+f"(c[1]), "+f"(c[2]), "+f"(c[3])
        : "f"(a0), "f"(a1), "f"(a2), "f"(a3), "f"(b0), "f"(b1));
}

__device__ __forceinline__ float2 unpack_bf2(unsigned w) {
    __nv_bfloat162 h = *reinterpret_cast<__nv_bfloat162*>(&w);
    return __bfloat1622float2(h);
}
__device__ __forceinline__ unsigned pack_bf2(float lo, float hi) {
    __nv_bfloat162 h = __floats2bfloat162_rn(lo, hi);
    return *reinterpret_cast<unsigned*>(&h);
}

// One 32x64x64 bf16 GEMM phase + fp32 epilogue division, 8 warps.
// Warp (rb = wid&1, cb = wid>>1) owns rows 16*rb..+16, cols 16*cb..+16.
// out[r][c] = sum_k A[r][k] * Bt[c][k];  Dst = Q / out (bf16).
__device__ __forceinline__ void mma_div_phase(
    const unsigned* __restrict__ A32, const unsigned* __restrict__ B32,
    int bstw, const unsigned* __restrict__ Q32, unsigned* __restrict__ D32,
    int wid, int lane)
{
    const int rb = wid & 1, cb = wid >> 1;
    const int g = lane >> 2, tg = lane & 3;
    const int r0 = rb * 16;
    float acc[2][4] = {};
    const int abase = (r0 + g) * STW + tg;
#pragma unroll
    for (int kc = 0; kc < 4; kc++) {
        unsigned a0 = A32[abase + 8 * kc];
        unsigned a1 = A32[abase + 8 * STW + 8 * kc];
        unsigned a2 = A32[abase + 8 * kc + 4];
        unsigned a3 = A32[abase + 8 * STW + 8 * kc + 4];
#pragma unroll
        for (int t = 0; t < 2; t++) {
            int bbase = (cb * 16 + 8 * t + g) * bstw + tg;
            unsigned b0 = B32[bbase + 8 * kc];
            unsigned b1 = B32[bbase + 8 * kc + 4];
            mma_bf16(acc[t], a0, a1, a2, a3, b0, b1);
        }
    }
#pragma unroll
    for (int t = 0; t < 2; t++) {
        int colw = cb * 8 + 4 * t + tg;
        int rlo = r0 + g, rhi = rlo + 8;
        float2 ql = unpack_bf2(Q32[rlo * STW + colw]);
        float2 qh = unpack_bf2(Q32[rhi * STW + colw]);
        D32[rlo * STW + colw] = pack_bf2(__fdividef(ql.x, acc[t][0]),
                                         __fdividef(ql.y, acc[t][1]));
        D32[rhi * STW + colw] = pack_bf2(__fdividef(qh.x, acc[t][2]),
                                         __fdividef(qh.y, acc[t][3]));
    }
}

__global__ __launch_bounds__(256, 2)
void emd_main(const float* __restrict__ f10, const float* __restrict__ f11,
              const float* __restrict__ f20, const float* __restrict__ f21,
              float* __restrict__ out)
{
    extern __shared__ char smb[];
    const int blk   = blockIdx.x;          // 0..255
    const int pair  = blk >> 7;
    const int i     = (blk >> 1) & 63;
    const int abase = (blk & 1) * 32;      // this block's a-row half
    const float* __restrict__ X1g = pair ? f11 : f10;
    const float* __restrict__ X2g = pair ? f21 : f20;

    const int tid  = threadIdx.x;
    const int lane = tid & 31;
    const int wid  = tid >> 5;        // 0..7
    const int rbid = (wid & 1) + 1;   // named barrier id for this row group

    float* sX1 = (float*)(smb + OB_X1);
    float* sX2 = (float*)(smb + OB_X2);
    float* sC  = (float*)(smb + OB_C);
    float* sI1 = (float*)(smb + OB_I1);
    float* sI2 = (float*)(smb + OB_I2);
    float* sRS = (float*)(smb + OB_RS);
    float* sRed = (float*)(smb + OB_RED);
    int*   sFlag = (int*)(smb + OB_FLAG);
    __nv_bfloat16* sQ1b = (__nv_bfloat16*)(smb + OB_Q1B);
    __nv_bfloat16* sQ2b = (__nv_bfloat16*)(smb + OB_Q2B);
    __nv_bfloat16* sEb  = (__nv_bfloat16*)(smb + OB_EB);
    __nv_bfloat16* sETb = (__nv_bfloat16*)(smb + OB_ETB);
    __nv_bfloat16* sGb  = (__nv_bfloat16*)(smb + OB_GB);
    unsigned* Q1_32 = (unsigned*)(smb + OB_Q1B);
    unsigned* Q2_32 = (unsigned*)(smb + OB_Q2B);
    unsigned* E_32  = (unsigned*)(smb + OB_EB);
    unsigned* ET_32 = (unsigned*)(smb + OB_ETB);
    unsigned* G_32  = (unsigned*)(smb + OB_GB);
    unsigned* EU_32 = (unsigned*)(smb + OB_EUB);
    unsigned* EV_32 = (unsigned*)(smb + OB_EVB);

    // ---- load tiles (tf32-prerounded, stride 68); inverse norms inline ----
    {
        const float4* g1 = (const float4*)(X1g + i * 4096);
        const float4* g2 = (const float4*)(X2g + i * 4096);
#pragma unroll
        for (int m = 0; m < 4; m++) {
            int v = tid + m * 256;
            int r = v >> 4;
            int c = (v & 15) << 2;
            float4 a = g1[v];
            float4 b = g2[v];
            float4 ar; ar.x = tf32r(a.x); ar.y = tf32r(a.y);
                       ar.z = tf32r(a.z); ar.w = tf32r(a.w);
            float4 br; br.x = tf32r(b.x); br.y = tf32r(b.y);
                       br.z = tf32r(b.z); br.w = tf32r(b.w);
            *(float4*)(sX1 + r * STF + c) = ar;
            *(float4*)(sX2 + r * STF + c) = br;
            float s1 = a.x * a.x + a.y * a.y + a.z * a.z + a.w * a.w;
            float s2 = b.x * b.x + b.y * b.y + b.z * b.z + b.w * b.w;
#pragma unroll
            for (int o = 8; o; o >>= 1) {
                s1 += __shfl_xor_sync(~0u, s1, o);
                s2 += __shfl_xor_sync(~0u, s2, o);
            }
            if ((tid & 15) == 0) {
                sI1[r] = 1.0f / fmaxf(sqrtf(s1), 1e-8f);
                sI2[r] = 1.0f / fmaxf(sqrtf(s2), 1e-8f);
            }
        }
    }

    // ---- softmax -> q (bf16) for our 32 a-rows. No max-subtract (N(0,1)
    //      inputs; exp safe in fp32, softmax identical). ----
    {
        float v1a[4], v1b[4], v2a[4], v2b[4];
#pragma unroll
        for (int r4 = 0; r4 < 4; r4++) {
            int a = abase + wid * 4 + r4;
            const float* r1 = X1g + (a * 64 + i) * 64;
            const float* r2 = X2g + (a * 64 + i) * 64;
            v1a[r4] = r1[lane]; v1b[r4] = r1[lane + 32];
            v2a[r4] = r2[lane]; v2b[r4] = r2[lane + 32];
        }
#pragma unroll
        for (int r4 = 0; r4 < 4; r4++) {
            int al = wid * 4 + r4;                    // local a-row
            float e1a = __expf(v1a[r4]), e1b = __expf(v1b[r4]);
            float e2a = __expf(v2a[r4]), e2b = __expf(v2b[r4]);
            float s1 = e1a + e1b;
            float s2 = e2a + e2b;
#pragma unroll
            for (int o = 16; o; o >>= 1) {
                s1 += __shfl_xor_sync(~0u, s1, o);
                s2 += __shfl_xor_sync(~0u, s2, o);
            }
            float i1 = __fdividef(1.0f, s1);
            float i2 = __fdividef(1.0f, s2);
            sQ1b[al * 72 + lane]      = __float2bfloat16(e1a * i1 + 1e-12f);
            sQ1b[al * 72 + lane + 32] = __float2bfloat16(e1b * i1 + 1e-12f);
            sQ2b[al * 72 + lane]      = __float2bfloat16(e2a * i2 + 1e-12f);
            sQ2b[al * 72 + lane + 32] = __float2bfloat16(e2b * i2 + 1e-12f);
        }
    }
    __syncthreads();

    // ---- C = 1 - cosine via tf32 mma (full 64x64; warp = 16 rows x 32 cols) ----
    {
        const int rbc = wid & 3, cbc = wid >> 2;      // 4 row blocks, 2 col blocks
        const int g = lane >> 2, tg = lane & 3;
        const int r0 = rbc * 16;
        float acc[4][4] = {};
        const int abase_ = (r0 + g) * STF + tg;
#pragma unroll
        for (int kc = 0; kc < 8; kc++) {
            float a0 = sX1[abase_ + 8 * kc];
            float a1 = sX1[abase_ + 8 * STF + 8 * kc];
            float a2 = sX1[abase_ + 8 * kc + 4];
            float a3 = sX1[abase_ + 8 * STF + 8 * kc + 4];
#pragma unroll
            for (int t = 0; t < 4; t++) {
                int bbase = (cbc * 32 + 8 * t + g) * STF + tg;
                float b0 = sX2[bbase + 8 * kc];
                float b1 = sX2[bbase + 8 * kc + 4];
                mma_tf32(acc[t], a0, a1, a2, a3, b0, b1);
            }
        }
        int rlo = r0 + g, rhi = rlo + 8;
        float i1lo = sI1[rlo], i1hi = sI1[rhi];
#pragma unroll
        for (int t = 0; t < 4; t++) {
            int col = cbc * 32 + 8 * t + 2 * tg;
            float i2a = sI2[col], i2b = sI2[col + 1];
            float2 lo, hi;
            lo.x = 1.0f - acc[t][0] * i1lo * i2a;
            lo.y = 1.0f - acc[t][1] * i1lo * i2b;
            hi.x = 1.0f - acc[t][2] * i1hi * i2a;
            hi.y = 1.0f - acc[t][3] * i1hi * i2b;
            *(float2*)(sC + rlo * STF + col) = lo;
            *(float2*)(sC + rhi * STF + col) = hi;
        }
    }
    __syncthreads();   // X1/X2 dead from here; E/ET/G alias them

    // ---- fused: per-row minmax -> normalize -> E, E^T, G, 1/rowsum ----
#pragma unroll 1
    for (int r8 = 0; r8 < 8; r8++) {
        int j = wid * 8 + r8;
        float c0v = sC[j * STF + lane];
        float c1v = sC[j * STF + 32 + lane];
        float mn = fminf(c0v, c1v), mx = fmaxf(c0v, c1v);
#pragma unroll
        for (int o = 16; o; o >>= 1) {
            mn = fminf(mn, __shfl_xor_sync(~0u, mn, o));
            mx = fmaxf(mx, __shfl_xor_sync(~0u, mx, o));
        }
        float rinv = 1.0f / (mx - mn);
        float cn0 = (c0v - mn) * rinv;
        float cn1 = (c1v - mn) * rinv;
        float e0 = __expf(-2.0f * cn0);
        float e1 = __expf(-2.0f * cn1);
        sEb[j * 72 + lane]      = __float2bfloat16(e0);
        sEb[j * 72 + lane + 32] = __float2bfloat16(e1);
        sGb[j * 72 + lane]      = __float2bfloat16(e0 * cn0);
        sGb[j * 72 + lane + 32] = __float2bfloat16(e1 * cn1);
        sETb[lane * 74 + j]        = __float2bfloat16(e0);
        sETb[(lane + 32) * 74 + j] = __float2bfloat16(e1);
        float s = e0 + e1;
#pragma unroll
        for (int o = 16; o; o >>= 1) s += __shfl_xor_sync(~0u, s, o);
        if (lane == 0) sRS[j] = __fdividef(1.0f, s);
    }
    __syncthreads();

    // ---- EU0 = q1 * (1/rowsumE), local 32 rows ----
    {
        int a = tid >> 3, j0 = (tid & 7) * 8;
#pragma unroll
        for (int p = 0; p < 4; p++) {
            float2 q = unpack_bf2(Q1_32[a * STW + (j0 >> 1) + p]);
            EU_32[a * STW + (j0 >> 1) + p] =
                pack_bf2(q.x * sRS[j0 + 2 * p], q.y * sRS[j0 + 2 * p + 1]);
        }
    }
    __syncthreads();

    // ---- Sinkhorn: 5 v-phases, 4 u-phases; 2 row-group named barriers ----
#pragma unroll 1
    for (int it = 0; it < 5; it++) {
        // v: T[a][k] = sum_j EU[a][j] * ET[k][j];  EV = Q2 / T
        mma_div_phase(EU_32, ET_32, STTW, Q2_32, EV_32, wid, lane);
        asm volatile("bar.sync %0, 128;" :: "r"(rbid) : "memory");
        if (it == 4) break;
        // u: S[a][j] = sum_k EV[a][k] * E[j][k];  EU = Q1 / S
        mma_div_phase(EV_32, E_32, STW, Q1_32, EU_32, wid, lane);
        asm volatile("bar.sync %0, 128;" :: "r"(rbid) : "memory");
    }

    // ---- final: T2 = EV @ G^T;  loss = sum EU .* T2 ----
    float local = 0.0f;
    {
        const int rb = wid & 1, cb = wid >> 1;
        const int g = lane >> 2, tg = lane & 3;
        const int r0 = rb * 16;
        float acc[2][4] = {};
        const int abase_ = (r0 + g) * STW + tg;
#pragma unroll
        for (int kc = 0; kc < 4; kc++) {
            unsigned a0_ = EV_32[abase_ + 8 * kc];
            unsigned a1_ = EV_32[abase_ + 8 * STW + 8 * kc];
            unsigned a2_ = EV_32[abase_ + 8 * kc + 4];
            unsigned a3_ = EV_32[abase_ + 8 * STW + 8 * kc + 4];
#pragma unroll
            for (int tt = 0; tt < 2; tt++) {
                int bbase = (cb * 16 + 8 * tt + g) * STW + tg;
                mma_bf16(acc[tt], a0_, a1_, a2_, a3_,
                         G_32[bbase + 8 * kc], G_32[bbase + 8 * kc + 4]);
            }
        }
#pragma unroll
        for (int tt = 0; tt < 2; tt++) {
            int colw = cb * 8 + 4 * tt + tg;
            int rlo = r0 + g, rhi = rlo + 8;
            float2 el = unpack_bf2(EU_32[rlo * STW + colw]);
            float2 eh = unpack_bf2(EU_32[rhi * STW + colw]);
            local += el.x * acc[tt][0] + el.y * acc[tt][1]
                   + eh.x * acc[tt][2] + eh.y * acc[tt][3];
        }
    }
#pragma unroll
    for (int o = 16; o; o >>= 1) local += __shfl_xor_sync(~0u, local, o);
    if (lane == 0) sRed[wid] = local;
    __syncthreads();

    // ---- publish partial; last block reduces deterministically ----
    if (tid == 0) {
        float tt = 0.0f;
#pragma unroll
        for (int w = 0; w < 8; w++) tt += sRed[w];
        g_partials[blk] = tt;
        __threadfence();
        unsigned int old = atomicAdd(&g_count, 1u);
        sFlag[0] = (old == 255u);
    }
    __syncthreads();
    if (sFlag[0] && wid == 0) {
        __threadfence();
        float v = 0.0f;
#pragma unroll
        for (int s = 0; s < 8; s++) v += g_partials[lane + 32 * s];
#pragma unroll
        for (int o = 16; o; o >>= 1) v += __shfl_xor_sync(~0u, v, o);
        if (lane == 0) {
            out[0] = v * (1.0f / 8192.0f);
            g_count = 0;
        }
    }
}

extern "C" void kernel_launch(void* const* d_in, const int* in_sizes, int n_in,
                              void* d_out, int out_size)
{
    (void)in_sizes; (void)n_in; (void)out_size;
    cudaFuncSetAttribute(emd_main, cudaFuncAttributeMaxDynamicSharedMemorySize, SMEM_BYTES);
    emd_main<<<256, 256, SMEM_BYTES>>>((const float*)d_in[0], (const float*)d_in[1],
                                       (const float*)d_in[2], (const float*)d_in[3],
                                       (float*)d_out);
}

// round 11
// speedup vs baseline: 1.1212x; 1.1212x over previous
#include <cuda_runtime.h>
#include <cuda_bf16.h>

// ---------------------------------------------------------------------------
// EMD loss (multiplicative Sinkhorn, 2*eps == 1), full tensor-core core.
//   C = row-minmax-norm(1 - cos(x1[i],x2[i]))   [tf32 mma.m16n8k8]
//   E = exp(-2C);  eu0 = q1/rowsum(E);
//   {ev = q2/(eu@E) ; eu = q1/(ev@E^T)} x4 ;
//   final fused: T = eu@E (per col k), W = eu@(E.*C) ; loss += sum (q2/T).*W
// 128 blocks x 512 threads; Sinkhorn syncs via 4-warp row-group named
// barriers; all global loads prefetched before any smem work.
// ---------------------------------------------------------------------------

#define SMEM_BYTES 118144

#define OB_X1    0        // f32(tf32) x1 [j][h] stride 68  (17408)
#define OB_X2    17408    // f32(tf32) x2 [k][h] stride 68  (17408)
#define OB_C     34816    // f32 C [j][k] stride 68         (17408)
#define OB_Q1B   52224    // bf16 q1 [a][j] stride 72       (9216)
#define OB_Q2B   61440    // bf16 q2 [a][k]                 (9216)
#define OB_EB    70656    // bf16 E  [j][k] stride 72       (9216)
#define OB_ETB   79872    // bf16 E^T [k][j] stride 74      (9472)
#define OB_GTB   89344    // bf16 (E.*C)^T [k][j] stride 74 (9472)
#define OB_EUB   98816    // bf16 eu [a][j] stride 72       (9216)
#define OB_EVB   108032   // bf16 ev [a][k]                 (9216)
#define OB_I1    117248
#define OB_I2    117504
#define OB_RS    117760
#define OB_RED   118016
#define OB_FLAG  118080

#define STF 68            // fp32 row stride (words)
#define STW 36            // bf16 row stride in 32-bit words
#define STTW 37           // E^T / G^T row stride in words

__device__ float g_partials[128];
__device__ unsigned int g_count = 0;

__device__ __forceinline__ float tf32r(float x) {
    float r; asm("cvt.rna.tf32.f32 %0, %1;" : "=f"(r) : "f"(x)); return r;
}

__device__ __forceinline__ void mma_bf16(float c[4], unsigned a0, unsigned a1,
                                         unsigned a2, unsigned a3,
                                         unsigned b0, unsigned b1)
{
    asm volatile(
        "mma.sync.aligned.m16n8k16.row.col.f32.bf16.bf16.f32 "
        "{%0,%1,%2,%3}, {%4,%5,%6,%7}, {%8,%9}, {%0,%1,%2,%3};"
        : "+f"(c[0]), "+f"(c[1]), "+f"(c[2]), "+f"(c[3])
        : "r"(a0), "r"(a1), "r"(a2), "r"(a3), "r"(b0), "r"(b1));
}

__device__ __forceinline__ void mma_tf32(float c[4], float a0, float a1,
                                         float a2, float a3, float b0, float b1)
{
    asm volatile(
        "mma.sync.aligned.m16n8k8.row.col.f32.tf32.tf32.f32 "
        "{%0,%1,%2,%3}, {%4,%5,%6,%7}, {%8,%9}, {%0,%1,%2,%3};"
        : "+f"(c[0]), "+f"(c[1]), "+f"(c[2]), "+f"(c[3])
        : "f"(a0), "f"(a1), "f"(a2), "f"(a3), "f"(b0), "f"(b1));
}

__device__ __forceinline__ float2 unpack_bf2(unsigned w) {
    __nv_bfloat162 h = *reinterpret_cast<__nv_bfloat162*>(&w);
    return __bfloat1622float2(h);
}
__device__ __forceinline__ unsigned pack_bf2(float lo, float hi) {
    __nv_bfloat162 h = __floats2bfloat162_rn(lo, hi);
    return *reinterpret_cast<unsigned*>(&h);
}

// One 64x64x64 bf16 GEMM phase + fp32 epilogue division, 16 warps.
// out[r][c] = sum_k A[r][k] * Bt[c][k];  Dst = Q / out (bf16).
__device__ __forceinline__ void mma_div_phase(
    const unsigned* __restrict__ A32, const unsigned* __restrict__ B32,
    int bstw, const unsigned* __restrict__ Q32, unsigned* __restrict__ D32,
    int wid, int lane)
{
    const int rb = wid & 3, cb = wid >> 2;
    const int g = lane >> 2, tg = lane & 3;
    const int r0 = rb * 16;
    float acc[2][4] = {};
    const int abase = (r0 + g) * STW + tg;
#pragma unroll
    for (int kc = 0; kc < 4; kc++) {
        unsigned a0 = A32[abase + 8 * kc];
        unsigned a1 = A32[abase + 8 * STW + 8 * kc];
        unsigned a2 = A32[abase + 8 * kc + 4];
        unsigned a3 = A32[abase + 8 * STW + 8 * kc + 4];
#pragma unroll
        for (int t = 0; t < 2; t++) {
            int bbase = (cb * 16 + 8 * t + g) * bstw + tg;
            unsigned b0 = B32[bbase + 8 * kc];
            unsigned b1 = B32[bbase + 8 * kc + 4];
            mma_bf16(acc[t], a0, a1, a2, a3, b0, b1);
        }
    }
#pragma unroll
    for (int t = 0; t < 2; t++) {
        int colw = cb * 8 + 4 * t + tg;
        int rlo = r0 + g, rhi = rlo + 8;
        float2 ql = unpack_bf2(Q32[rlo * STW + colw]);
        float2 qh = unpack_bf2(Q32[rhi * STW + colw]);
        D32[rlo * STW + colw] = pack_bf2(__fdividef(ql.x, acc[t][0]),
                                         __fdividef(ql.y, acc[t][1]));
        D32[rhi * STW + colw] = pack_bf2(__fdividef(qh.x, acc[t][2]),
                                         __fdividef(qh.y, acc[t][3]));
    }
}

__global__ __launch_bounds__(512, 1)
void emd_main(const float* __restrict__ f10, const float* __restrict__ f11,
              const float* __restrict__ f20, const float* __restrict__ f21,
              float* __restrict__ out)
{
    extern __shared__ char smb[];
    const int blk  = blockIdx.x;
    const int pair = blk >> 6;
    const int i    = blk & 63;
    const float* __restrict__ X1g = pair ? f11 : f10;
    const float* __restrict__ X2g = pair ? f21 : f20;

    const int tid  = threadIdx.x;
    const int lane = tid & 31;
    const int wid  = tid >> 5;        // 0..15
    const int rbid = (wid & 3) + 1;   // named barrier id for this row group

    float* sX1 = (float*)(smb + OB_X1);
    float* sX2 = (float*)(smb + OB_X2);
    float* sC  = (float*)(smb + OB_C);
    float* sI1 = (float*)(smb + OB_I1);
    float* sI2 = (float*)(smb + OB_I2);
    float* sRS = (float*)(smb + OB_RS);
    float* sRed = (float*)(smb + OB_RED);
    int*   sFlag = (int*)(smb + OB_FLAG);
    __nv_bfloat16* sQ1b = (__nv_bfloat16*)(smb + OB_Q1B);
    __nv_bfloat16* sQ2b = (__nv_bfloat16*)(smb + OB_Q2B);
    __nv_bfloat16* sEb  = (__nv_bfloat16*)(smb + OB_EB);
    __nv_bfloat16* sETb = (__nv_bfloat16*)(smb + OB_ETB);
    __nv_bfloat16* sGTb = (__nv_bfloat16*)(smb + OB_GTB);
    unsigned* Q1_32 = (unsigned*)(smb + OB_Q1B);
    unsigned* Q2_32 = (unsigned*)(smb + OB_Q2B);
    unsigned* E_32  = (unsigned*)(smb + OB_EB);
    unsigned* ET_32 = (unsigned*)(smb + OB_ETB);
    unsigned* GT_32 = (unsigned*)(smb + OB_GTB);
    unsigned* EU_32 = (unsigned*)(smb + OB_EUB);
    unsigned* EV_32 = (unsigned*)(smb + OB_EVB);

    // ---- prefetch ALL global loads first (tile + softmax rows) ----
    float4 ta0, ta1, tb0, tb1;
    {
        const float4* g1 = (const float4*)(X1g + i * 4096);
        const float4* g2 = (const float4*)(X2g + i * 4096);
        ta0 = g1[tid]; ta1 = g1[tid + 512];
        tb0 = g2[tid]; tb1 = g2[tid + 512];
    }
    float v1a[4], v1b[4], v2a[4], v2b[4];
#pragma unroll
    for (int r4 = 0; r4 < 4; r4++) {
        int a = wid * 4 + r4;
        const float* r1 = X1g + (a * 64 + i) * 64;
        const float* r2 = X2g + (a * 64 + i) * 64;
        v1a[r4] = r1[lane]; v1b[r4] = r1[lane + 32];
        v2a[r4] = r2[lane]; v2b[r4] = r2[lane + 32];
    }

    // ---- stage tiles (tf32-prerounded, stride 68); inverse norms inline ----
    {
#pragma unroll
        for (int m = 0; m < 2; m++) {
            int v = tid + m * 512;
            int r = v >> 4;
            int c = (v & 15) << 2;
            float4 a = m ? ta1 : ta0;
            float4 b = m ? tb1 : tb0;
            float4 ar; ar.x = tf32r(a.x); ar.y = tf32r(a.y);
                       ar.z = tf32r(a.z); ar.w = tf32r(a.w);
            float4 br; br.x = tf32r(b.x); br.y = tf32r(b.y);
                       br.z = tf32r(b.z); br.w = tf32r(b.w);
            *(float4*)(sX1 + r * STF + c) = ar;
            *(float4*)(sX2 + r * STF + c) = br;
            float s1 = a.x * a.x + a.y * a.y + a.z * a.z + a.w * a.w;
            float s2 = b.x * b.x + b.y * b.y + b.z * b.z + b.w * b.w;
#pragma unroll
            for (int o = 8; o; o >>= 1) {
                s1 += __shfl_xor_sync(~0u, s1, o);
                s2 += __shfl_xor_sync(~0u, s2, o);
            }
            if ((tid & 15) == 0) {
                sI1[r] = 1.0f / fmaxf(sqrtf(s1), 1e-8f);
                sI2[r] = 1.0f / fmaxf(sqrtf(s2), 1e-8f);
            }
        }
    }

    // ---- softmax -> q (bf16). No max-subtract: inputs are N(0,1), exp is
    //      safe in fp32; softmax(x) == exp(x)/sum(exp(x)) exactly. ----
#pragma unroll
    for (int r4 = 0; r4 < 4; r4++) {
        int a = wid * 4 + r4;
        float e1a = __expf(v1a[r4]), e1b = __expf(v1b[r4]);
        float e2a = __expf(v2a[r4]), e2b = __expf(v2b[r4]);
        float s1 = e1a + e1b;
        float s2 = e2a + e2b;
#pragma unroll
        for (int o = 16; o; o >>= 1) {
            s1 += __shfl_xor_sync(~0u, s1, o);
            s2 += __shfl_xor_sync(~0u, s2, o);
        }
        float i1 = __fdividef(1.0f, s1);
        float i2 = __fdividef(1.0f, s2);
        sQ1b[a * 72 + lane]      = __float2bfloat16(e1a * i1 + 1e-12f);
        sQ1b[a * 72 + lane + 32] = __float2bfloat16(e1b * i1 + 1e-12f);
        sQ2b[a * 72 + lane]      = __float2bfloat16(e2a * i2 + 1e-12f);
        sQ2b[a * 72 + lane + 32] = __float2bfloat16(e2b * i2 + 1e-12f);
    }
    __syncthreads();

    // ---- C = 1 - cosine via tf32 mma (A = x1 rows, Bt = x2 rows) ----
    {
        const int rb = wid & 3, cb = wid >> 2;
        const int g = lane >> 2, tg = lane & 3;
        const int r0 = rb * 16;
        float acc[2][4] = {};
        const int abase = (r0 + g) * STF + tg;
#pragma unroll
        for (int kc = 0; kc < 8; kc++) {
            float a0 = sX1[abase + 8 * kc];
            float a1 = sX1[abase + 8 * STF + 8 * kc];
            float a2 = sX1[abase + 8 * kc + 4];
            float a3 = sX1[abase + 8 * STF + 8 * kc + 4];
#pragma unroll
            for (int t = 0; t < 2; t++) {
                int bbase = (cb * 16 + 8 * t + g) * STF + tg;
                float b0 = sX2[bbase + 8 * kc];
                float b1 = sX2[bbase + 8 * kc + 4];
                mma_tf32(acc[t], a0, a1, a2, a3, b0, b1);
            }
        }
        int rlo = r0 + g, rhi = rlo + 8;
        float i1lo = sI1[rlo], i1hi = sI1[rhi];
#pragma unroll
        for (int t = 0; t < 2; t++) {
            int col = cb * 16 + 8 * t + 2 * tg;
            float i2a = sI2[col], i2b = sI2[col + 1];
            float2 lo, hi;
            lo.x = 1.0f - acc[t][0] * i1lo * i2a;
            lo.y = 1.0f - acc[t][1] * i1lo * i2b;
            hi.x = 1.0f - acc[t][2] * i1hi * i2a;
            hi.y = 1.0f - acc[t][3] * i1hi * i2b;
            *(float2*)(sC + rlo * STF + col) = lo;
            *(float2*)(sC + rhi * STF + col) = hi;
        }
    }
    __syncthreads();

    // ---- fused: per-row minmax -> normalize -> E, E^T, G^T, 1/rowsum ----
#pragma unroll 1
    for (int r4 = 0; r4 < 4; r4++) {
        int j = wid * 4 + r4;
        float c0v = sC[j * STF + lane];
        float c1v = sC[j * STF + 32 + lane];
        float mn = fminf(c0v, c1v), mx = fmaxf(c0v, c1v);
#pragma unroll
        for (int o = 16; o; o >>= 1) {
            mn = fminf(mn, __shfl_xor_sync(~0u, mn, o));
            mx = fmaxf(mx, __shfl_xor_sync(~0u, mx, o));
        }
        float rinv = 1.0f / (mx - mn);
        float cn0 = (c0v - mn) * rinv;
        float cn1 = (c1v - mn) * rinv;
        float e0 = __expf(-2.0f * cn0);
        float e1 = __expf(-2.0f * cn1);
        sEb[j * 72 + lane]      = __float2bfloat16(e0);
        sEb[j * 72 + lane + 32] = __float2bfloat16(e1);
        sETb[lane * 74 + j]        = __float2bfloat16(e0);
        sETb[(lane + 32) * 74 + j] = __float2bfloat16(e1);
        sGTb[lane * 74 + j]        = __float2bfloat16(e0 * cn0);
        sGTb[(lane + 32) * 74 + j] = __float2bfloat16(e1 * cn1);
        float s = e0 + e1;
#pragma unroll
        for (int o = 16; o; o >>= 1) s += __shfl_xor_sync(~0u, s, o);
        if (lane == 0) sRS[j] = __fdividef(1.0f, s);
    }
    __syncthreads();

    // ---- EU0 = q1 * (1/rowsumE) ----
    {
        int a = tid >> 3, j0 = (tid & 7) * 8;
#pragma unroll
        for (int p = 0; p < 4; p++) {
            float2 q = unpack_bf2(Q1_32[a * STW + (j0 >> 1) + p]);
            EU_32[a * STW + (j0 >> 1) + p] =
                pack_bf2(q.x * sRS[j0 + 2 * p], q.y * sRS[j0 + 2 * p + 1]);
        }
    }
    __syncthreads();

    // ---- Sinkhorn: 4x {v-phase, u-phase}, row-group named barriers ----
#pragma unroll 1
    for (int it = 0; it < 4; it++) {
        // v: T[a][k] = sum_j EU[a][j] * ET[k][j];  EV = Q2 / T
        mma_div_phase(EU_32, ET_32, STTW, Q2_32, EV_32, wid, lane);
        asm volatile("bar.sync %0, 128;" :: "r"(rbid) : "memory");
        // u: S[a][j] = sum_k EV[a][k] * E[j][k];  EU = Q1 / S
        mma_div_phase(EV_32, E_32, STW, Q1_32, EU_32, wid, lane);
        asm volatile("bar.sync %0, 128;" :: "r"(rbid) : "memory");
    }

    // ---- fused final v-phase + loss:
    //      T[a][k] = eu@E (via ET), W[a][k] = eu@(E.*C) (via GT);
    //      loss += sum (q2/T) .* W  -- EV never materialized. ----
    float local = 0.0f;
    {
        const int rb = wid & 3, cb = wid >> 2;
        const int g = lane >> 2, tg = lane & 3;
        const int r0 = rb * 16;
        float accT[2][4] = {}, accW[2][4] = {};
        const int abase = (r0 + g) * STW + tg;
#pragma unroll
        for (int kc = 0; kc < 4; kc++) {
            unsigned a0 = EU_32[abase + 8 * kc];
            unsigned a1 = EU_32[abase + 8 * STW + 8 * kc];
            unsigned a2 = EU_32[abase + 8 * kc + 4];
            unsigned a3 = EU_32[abase + 8 * STW + 8 * kc + 4];
#pragma unroll
            for (int t = 0; t < 2; t++) {
                int bbase = (cb * 16 + 8 * t + g) * STTW + tg;
                mma_bf16(accT[t], a0, a1, a2, a3,
                         ET_32[bbase + 8 * kc], ET_32[bbase + 8 * kc + 4]);
                mma_bf16(accW[t], a0, a1, a2, a3,
                         GT_32[bbase + 8 * kc], GT_32[bbase + 8 * kc + 4]);
            }
        }
#pragma unroll
        for (int t = 0; t < 2; t++) {
            int colw = cb * 8 + 4 * t + tg;
            int rlo = r0 + g, rhi = rlo + 8;
            float2 ql = unpack_bf2(Q2_32[rlo * STW + colw]);
            float2 qh = unpack_bf2(Q2_32[rhi * STW + colw]);
            local += __fdividef(ql.x, accT[t][0]) * accW[t][0]
                   + __fdividef(ql.y, accT[t][1]) * accW[t][1]
                   + __fdividef(qh.x, accT[t][2]) * accW[t][2]
                   + __fdividef(qh.y, accT[t][3]) * accW[t][3];
        }
    }
#pragma unroll
    for (int o = 16; o; o >>= 1) local += __shfl_xor_sync(~0u, local, o);
    if (lane == 0) sRed[wid] = local;
    __syncthreads();

    // ---- publish partial; last block reduces deterministically ----
    if (tid == 0) {
        float tt = 0.0f;
#pragma unroll
        for (int w = 0; w < 16; w++) tt += sRed[w];
        g_partials[blk] = tt;
        __threadfence();
        unsigned int old = atomicAdd(&g_count, 1u);
        sFlag[0] = (old == 127u);
    }
    __syncthreads();
    if (sFlag[0] && wid == 0) {
        __threadfence();
        float v = g_partials[lane] + g_partials[lane + 32]
                + g_partials[lane + 64] + g_partials[lane + 96];
#pragma unroll
        for (int o = 16; o; o >>= 1) v += __shfl_xor_sync(~0u, v, o);
        if (lane == 0) {
            out[0] = v * (1.0f / 8192.0f);
            g_count = 0;
        }
    }
}

extern "C" void kernel_launch(void* const* d_in, const int* in_sizes, int n_in,
                              void* d_out, int out_size)
{
    (void)in_sizes; (void)n_in; (void)out_size;
    cudaFuncSetAttribute(emd_main, cudaFuncAttributeMaxDynamicSharedMemorySize, SMEM_BYTES);
    emd_main<<<128, 512, SMEM_BYTES>>>((const float*)d_in[0], (const float*)d_in[1],
                                       (const float*)d_in[2], (const float*)d_in[3],
                                       (float*)d_out);
}

// round 12
// speedup vs baseline: 1.2786x; 1.1404x over previous
#include <cuda_runtime.h>
#include <cuda_bf16.h>

// ---------------------------------------------------------------------------
// EMD loss (multiplicative Sinkhorn, 2*eps == 1), register-resident core.
//   C = row-minmax-norm(1 - cos(x1[i],x2[i]))   [tf32 mma.m16n8k8]
//   E = exp(-2C);  eu0 = q1/rowsum(E);
//   {ev = q2/(eu@E) ; eu = q1/(ev@E^T)} x4 ; final fused T/W phase.
// 128 blocks x 512 threads. Sinkhorn: 4 warps (one per SMSP), each owns 16
// rows x 64 cols; mma accumulator fragments repack DIRECTLY into next-phase
// A fragments (acc c0..c3 layout == A-frag layout), so the whole 9-phase
// chain runs in registers with ZERO barriers / smem round-trips. B operands
// (E, E^T, G^T) + Q are read-only after one syncthreads.
// ---------------------------------------------------------------------------

#define SMEM_BYTES 99200

#define OB_X1    0        // f32(tf32) x1 [j][h] stride 68  (17408)
#define OB_X2    17408    // f32(tf32) x2 [k][h] stride 68  (17408)
#define OB_C     34816    // f32 C [j][k] stride 68         (17408)
#define OB_Q1B   52224    // bf16 q1 [a][j] stride 72       (9216)
#define OB_Q2B   61440    // bf16 q2 [a][k] stride 72       (9216)
#define OB_EB    70656    // bf16 E  [j][k] stride 72       (9216)
#define OB_ETB   79872    // bf16 E^T [k][j] stride 72      (9216)
#define OB_GTB   89088    // bf16 (E.*C)^T [k][j] stride 72 (9216)
#define OB_I1    98304
#define OB_I2    98560
#define OB_RS    98816
#define OB_RED   99072
#define OB_FLAG  99136

#define STF 68            // fp32 row stride (words)
#define STW 36            // bf16 row stride in 32-bit words (all bf16 bufs)

__device__ float g_partials[128];
__device__ unsigned int g_count = 0;

__device__ __forceinline__ float tf32r(float x) {
    float r; asm("cvt.rna.tf32.f32 %0, %1;" : "=f"(r) : "f"(x)); return r;
}

__device__ __forceinline__ void mma_bf16(float c[4], unsigned a0, unsigned a1,
                                         unsigned a2, unsigned a3,
                                         unsigned b0, unsigned b1)
{
    asm volatile(
        "mma.sync.aligned.m16n8k16.row.col.f32.bf16.bf16.f32 "
        "{%0,%1,%2,%3}, {%4,%5,%6,%7}, {%8,%9}, {%0,%1,%2,%3};"
        : "+f"(c[0]), "+f"(c[1]), "+f"(c[2]), "+f"(c[3])
        : "r"(a0), "r"(a1), "r"(a2), "r"(a3), "r"(b0), "r"(b1));
}

__device__ __forceinline__ void mma_tf32(float c[4], float a0, float a1,
                                         float a2, float a3, float b0, float b1)
{
    asm volatile(
        "mma.sync.aligned.m16n8k8.row.col.f32.tf32.tf32.f32 "
        "{%0,%1,%2,%3}, {%4,%5,%6,%7}, {%8,%9}, {%0,%1,%2,%3};"
        : "+f"(c[0]), "+f"(c[1]), "+f"(c[2]), "+f"(c[3])
        : "f"(a0), "f"(a1), "f"(a2), "f"(a3), "f"(b0), "f"(b1));
}

__device__ __forceinline__ float2 unpack_bf2(unsigned w) {
    __nv_bfloat162 h = *reinterpret_cast<__nv_bfloat162*>(&w);
    return __bfloat1622float2(h);
}
__device__ __forceinline__ unsigned pack_bf2(float lo, float hi) {
    __nv_bfloat162 h = __floats2bfloat162_rn(lo, hi);
    return *reinterpret_cast<unsigned*>(&h);
}

__global__ __launch_bounds__(512, 1)
void emd_main(const float* __restrict__ f10, const float* __restrict__ f11,
              const float* __restrict__ f20, const float* __restrict__ f21,
              float* __restrict__ out)
{
    extern __shared__ char smb[];
    const int blk  = blockIdx.x;
    const int pair = blk >> 6;
    const int i    = blk & 63;
    const float* __restrict__ X1g = pair ? f11 : f10;
    const float* __restrict__ X2g = pair ? f21 : f20;

    const int tid  = threadIdx.x;
    const int lane = tid & 31;
    const int wid  = tid >> 5;        // 0..15

    float* sX1 = (float*)(smb + OB_X1);
    float* sX2 = (float*)(smb + OB_X2);
    float* sC  = (float*)(smb + OB_C);
    float* sI1 = (float*)(smb + OB_I1);
    float* sI2 = (float*)(smb + OB_I2);
    float* sRS = (float*)(smb + OB_RS);
    float* sRed = (float*)(smb + OB_RED);
    int*   sFlag = (int*)(smb + OB_FLAG);
    __nv_bfloat16* sQ1b = (__nv_bfloat16*)(smb + OB_Q1B);
    __nv_bfloat16* sQ2b = (__nv_bfloat16*)(smb + OB_Q2B);
    __nv_bfloat16* sEb  = (__nv_bfloat16*)(smb + OB_EB);
    __nv_bfloat16* sETb = (__nv_bfloat16*)(smb + OB_ETB);
    __nv_bfloat16* sGTb = (__nv_bfloat16*)(smb + OB_GTB);
    unsigned* Q1_32 = (unsigned*)(smb + OB_Q1B);
    unsigned* Q2_32 = (unsigned*)(smb + OB_Q2B);
    unsigned* E_32  = (unsigned*)(smb + OB_EB);
    unsigned* ET_32 = (unsigned*)(smb + OB_ETB);
    unsigned* GT_32 = (unsigned*)(smb + OB_GTB);

    // ---- prefetch ALL global loads first (tile + softmax rows) ----
    float4 ta0, ta1, tb0, tb1;
    {
        const float4* g1 = (const float4*)(X1g + i * 4096);
        const float4* g2 = (const float4*)(X2g + i * 4096);
        ta0 = g1[tid]; ta1 = g1[tid + 512];
        tb0 = g2[tid]; tb1 = g2[tid + 512];
    }
    float v1a[4], v1b[4], v2a[4], v2b[4];
#pragma unroll
    for (int r4 = 0; r4 < 4; r4++) {
        int a = wid * 4 + r4;
        const float* r1 = X1g + (a * 64 + i) * 64;
        const float* r2 = X2g + (a * 64 + i) * 64;
        v1a[r4] = r1[lane]; v1b[r4] = r1[lane + 32];
        v2a[r4] = r2[lane]; v2b[r4] = r2[lane + 32];
    }

    // ---- stage tiles (tf32-prerounded, stride 68); inverse norms inline ----
    {
#pragma unroll
        for (int m = 0; m < 2; m++) {
            int v = tid + m * 512;
            int r = v >> 4;
            int c = (v & 15) << 2;
            float4 a = m ? ta1 : ta0;
            float4 b = m ? tb1 : tb0;
            float4 ar; ar.x = tf32r(a.x); ar.y = tf32r(a.y);
                       ar.z = tf32r(a.z); ar.w = tf32r(a.w);
            float4 br; br.x = tf32r(b.x); br.y = tf32r(b.y);
                       br.z = tf32r(b.z); br.w = tf32r(b.w);
            *(float4*)(sX1 + r * STF + c) = ar;
            *(float4*)(sX2 + r * STF + c) = br;
            float s1 = a.x * a.x + a.y * a.y + a.z * a.z + a.w * a.w;
            float s2 = b.x * b.x + b.y * b.y + b.z * b.z + b.w * b.w;
#pragma unroll
            for (int o = 8; o; o >>= 1) {
                s1 += __shfl_xor_sync(~0u, s1, o);
                s2 += __shfl_xor_sync(~0u, s2, o);
            }
            if ((tid & 15) == 0) {
                sI1[r] = 1.0f / fmaxf(sqrtf(s1), 1e-8f);
                sI2[r] = 1.0f / fmaxf(sqrtf(s2), 1e-8f);
            }
        }
    }

    // ---- softmax -> q (bf16). No max-subtract (N(0,1) inputs). ----
#pragma unroll
    for (int r4 = 0; r4 < 4; r4++) {
        int a = wid * 4 + r4;
        float e1a = __expf(v1a[r4]), e1b = __expf(v1b[r4]);
        float e2a = __expf(v2a[r4]), e2b = __expf(v2b[r4]);
        float s1 = e1a + e1b;
        float s2 = e2a + e2b;
#pragma unroll
        for (int o = 16; o; o >>= 1) {
            s1 += __shfl_xor_sync(~0u, s1, o);
            s2 += __shfl_xor_sync(~0u, s2, o);
        }
        float i1 = __fdividef(1.0f, s1);
        float i2 = __fdividef(1.0f, s2);
        sQ1b[a * 72 + lane]      = __float2bfloat16(e1a * i1 + 1e-12f);
        sQ1b[a * 72 + lane + 32] = __float2bfloat16(e1b * i1 + 1e-12f);
        sQ2b[a * 72 + lane]      = __float2bfloat16(e2a * i2 + 1e-12f);
        sQ2b[a * 72 + lane + 32] = __float2bfloat16(e2b * i2 + 1e-12f);
    }
    __syncthreads();

    // ---- C = 1 - cosine via tf32 mma (A = x1 rows, Bt = x2 rows) ----
    {
        const int rb = wid & 3, cb = wid >> 2;
        const int g = lane >> 2, tg = lane & 3;
        const int r0 = rb * 16;
        float acc[2][4] = {};
        const int abase = (r0 + g) * STF + tg;
#pragma unroll
        for (int kc = 0; kc < 8; kc++) {
            float a0 = sX1[abase + 8 * kc];
            float a1 = sX1[abase + 8 * STF + 8 * kc];
            float a2 = sX1[abase + 8 * kc + 4];
            float a3 = sX1[abase + 8 * STF + 8 * kc + 4];
#pragma unroll
            for (int t = 0; t < 2; t++) {
                int bbase = (cb * 16 + 8 * t + g) * STF + tg;
                float b0 = sX2[bbase + 8 * kc];
                float b1 = sX2[bbase + 8 * kc + 4];
                mma_tf32(acc[t], a0, a1, a2, a3, b0, b1);
            }
        }
        int rlo = r0 + g, rhi = rlo + 8;
        float i1lo = sI1[rlo], i1hi = sI1[rhi];
#pragma unroll
        for (int t = 0; t < 2; t++) {
            int col = cb * 16 + 8 * t + 2 * tg;
            float i2a = sI2[col], i2b = sI2[col + 1];
            float2 lo, hi;
            lo.x = 1.0f - acc[t][0] * i1lo * i2a;
            lo.y = 1.0f - acc[t][1] * i1lo * i2b;
            hi.x = 1.0f - acc[t][2] * i1hi * i2a;
            hi.y = 1.0f - acc[t][3] * i1hi * i2b;
            *(float2*)(sC + rlo * STF + col) = lo;
            *(float2*)(sC + rhi * STF + col) = hi;
        }
    }
    __syncthreads();

    // ---- fused: per-row minmax -> normalize -> E, E^T, G^T, 1/rowsum ----
#pragma unroll 1
    for (int r4 = 0; r4 < 4; r4++) {
        int j = wid * 4 + r4;
        float c0v = sC[j * STF + lane];
        float c1v = sC[j * STF + 32 + lane];
        float mn = fminf(c0v, c1v), mx = fmaxf(c0v, c1v);
#pragma unroll
        for (int o = 16; o; o >>= 1) {
            mn = fminf(mn, __shfl_xor_sync(~0u, mn, o));
            mx = fmaxf(mx, __shfl_xor_sync(~0u, mx, o));
        }
        float rinv = 1.0f / (mx - mn);
        float cn0 = (c0v - mn) * rinv;
        float cn1 = (c1v - mn) * rinv;
        float e0 = __expf(-2.0f * cn0);
        float e1 = __expf(-2.0f * cn1);
        sEb[j * 72 + lane]      = __float2bfloat16(e0);
        sEb[j * 72 + lane + 32] = __float2bfloat16(e1);
        sETb[lane * 72 + j]        = __float2bfloat16(e0);
        sETb[(lane + 32) * 72 + j] = __float2bfloat16(e1);
        sGTb[lane * 72 + j]        = __float2bfloat16(e0 * cn0);
        sGTb[(lane + 32) * 72 + j] = __float2bfloat16(e1 * cn1);
        float s = e0 + e1;
#pragma unroll
        for (int o = 16; o; o >>= 1) s += __shfl_xor_sync(~0u, s, o);
        if (lane == 0) sRS[j] = __fdividef(1.0f, s);
    }
    __syncthreads();
    // E / E^T / G^T / Q / rowsums are now read-only. No more block barriers
    // until the final reduction.

    // ---- register-resident Sinkhorn: warps 0..3 (one per SMSP), each owns
    //      rows r0..r0+15 x all 64 cols. Acc fragments repack into next
    //      A fragments (c0..c3 layout == A-frag layout). ----
    float local = 0.0f;
    if (wid < 4) {
        const int g = lane >> 2, tg = lane & 3;
        const int r0 = wid * 16;
        unsigned af[4][4];

        // EU0 = q1 * (1/rowsumE), built straight into A fragments.
#pragma unroll
        for (int kc = 0; kc < 4; kc++) {
            int j0 = 16 * kc + 2 * tg, j1 = j0 + 8;
            float2 qa = unpack_bf2(Q1_32[(r0 + g) * STW + 8 * kc + tg]);
            float2 qb = unpack_bf2(Q1_32[(r0 + g + 8) * STW + 8 * kc + tg]);
            float2 qc = unpack_bf2(Q1_32[(r0 + g) * STW + 8 * kc + tg + 4]);
            float2 qd = unpack_bf2(Q1_32[(r0 + g + 8) * STW + 8 * kc + tg + 4]);
            af[kc][0] = pack_bf2(qa.x * sRS[j0], qa.y * sRS[j0 + 1]);
            af[kc][1] = pack_bf2(qb.x * sRS[j0], qb.y * sRS[j0 + 1]);
            af[kc][2] = pack_bf2(qc.x * sRS[j1], qc.y * sRS[j1 + 1]);
            af[kc][3] = pack_bf2(qd.x * sRS[j1], qd.y * sRS[j1 + 1]);
        }

        const int qlo = (r0 + g) * STW;      // word base, row g
        const int qhi = (r0 + g + 8) * STW;  // word base, row g+8

        // 4x {v-phase (B=E^T, Q=q2), u-phase (B=E, Q=q1)}, all in registers.
#pragma unroll 1
        for (int it = 0; it < 4; it++) {
#pragma unroll
            for (int ph = 0; ph < 2; ph++) {
                const unsigned* B32 = ph ? E_32 : ET_32;
                const unsigned* Q32 = ph ? Q1_32 : Q2_32;
                float acc[8][4];
#pragma unroll
                for (int t = 0; t < 8; t++)
                    acc[t][0] = acc[t][1] = acc[t][2] = acc[t][3] = 0.0f;
#pragma unroll
                for (int kc = 0; kc < 4; kc++) {
#pragma unroll
                    for (int t = 0; t < 8; t++) {
                        int bbase = (8 * t + g) * STW + tg;
                        mma_bf16(acc[t], af[kc][0], af[kc][1],
                                 af[kc][2], af[kc][3],
                                 B32[bbase + 8 * kc], B32[bbase + 8 * kc + 4]);
                    }
                }
#pragma unroll
                for (int kc = 0; kc < 4; kc++) {
#pragma unroll
                    for (int h = 0; h < 2; h++) {
                        int t = 2 * kc + h;
                        float2 ql = unpack_bf2(Q32[qlo + 4 * t + tg]);
                        float2 qh = unpack_bf2(Q32[qhi + 4 * t + tg]);
                        af[kc][2 * h]     = pack_bf2(__fdividef(ql.x, acc[t][0]),
                                                     __fdividef(ql.y, acc[t][1]));
                        af[kc][2 * h + 1] = pack_bf2(__fdividef(qh.x, acc[t][2]),
                                                     __fdividef(qh.y, acc[t][3]));
                    }
                }
            }
        }

        // fused final v-phase: T = eu@E (via E^T), W = eu@(E.*C) (via G^T);
        // loss += sum (q2/T) .* W
        {
            float accT[8][4], accW[8][4];
#pragma unroll
            for (int t = 0; t < 8; t++) {
                accT[t][0] = accT[t][1] = accT[t][2] = accT[t][3] = 0.0f;
                accW[t][0] = accW[t][1] = accW[t][2] = accW[t][3] = 0.0f;
            }
#pragma unroll
            for (int kc = 0; kc < 4; kc++) {
#pragma unroll
                for (int t = 0; t < 8; t++) {
                    int bbase = (8 * t + g) * STW + tg;
                    mma_bf16(accT[t], af[kc][0], af[kc][1], af[kc][2], af[kc][3],
                             ET_32[bbase + 8 * kc], ET_32[bbase + 8 * kc + 4]);
                    mma_bf16(accW[t], af[kc][0], af[kc][1], af[kc][2], af[kc][3],
                             GT_32[bbase + 8 * kc], GT_32[bbase + 8 * kc + 4]);
                }
            }
#pragma unroll
            for (int t = 0; t < 8; t++) {
                float2 ql = unpack_bf2(Q2_32[qlo + 4 * t + tg]);
                float2 qh = unpack_bf2(Q2_32[qhi + 4 * t + tg]);
                local += __fdividef(ql.x, accT[t][0]) * accW[t][0]
                       + __fdividef(ql.y, accT[t][1]) * accW[t][1]
                       + __fdividef(qh.x, accT[t][2]) * accW[t][2]
                       + __fdividef(qh.y, accT[t][3]) * accW[t][3];
            }
        }
#pragma unroll
        for (int o = 16; o; o >>= 1) local += __shfl_xor_sync(~0u, local, o);
        if (lane == 0) sRed[wid] = local;
    }
    __syncthreads();

    // ---- publish partial; last block reduces deterministically ----
    if (tid == 0) {
        float tt = sRed[0] + sRed[1] + sRed[2] + sRed[3];
        g_partials[blk] = tt;
        __threadfence();
        unsigned int old = atomicAdd(&g_count, 1u);
        sFlag[0] = (old == 127u);
    }
    __syncthreads();
    if (sFlag[0] && wid == 0) {
        __threadfence();
        float v = g_partials[lane] + g_partials[lane + 32]
                + g_partials[lane + 64] + g_partials[lane + 96];
#pragma unroll
        for (int o = 16; o; o >>= 1) v += __shfl_xor_sync(~0u, v, o);
        if (lane == 0) {
            out[0] = v * (1.0f / 8192.0f);
            g_count = 0;
        }
    }
}

extern "C" void kernel_launch(void* const* d_in, const int* in_sizes, int n_in,
                              void* d_out, int out_size)
{
    (void)in_sizes; (void)n_in; (void)out_size;
    cudaFuncSetAttribute(emd_main, cudaFuncAttributeMaxDynamicSharedMemorySize, SMEM_BYTES);
    emd_main<<<128, 512, SMEM_BYTES>>>((const float*)d_in[0], (const float*)d_in[1],
                                       (const float*)d_in[2], (const float*)d_in[3],
                                       (float*)d_out);
}